// round 1
// baseline (speedup 1.0000x reference)
#include <cuda_runtime.h>

#define BB    8
#define NH    12
#define NTOK  1025
#define FT    768
#define FH    64
#define MROWS (BB*NTOK)   /* 8200 */
#define NDIST 3972

// ---- static scratch (no allocations allowed) ----
__device__ float g_q[(size_t)BB*NH*NTOK*FH];
__device__ float g_k[(size_t)BB*NH*NTOK*FH];
__device__ float g_v[(size_t)BB*NH*NTOK*FH];
__device__ float g_ao[(size_t)MROWS*FT];

// ============================================================
// Kernel 1: QKV GEMM.  C[m, c] = sum_k tokens[m,k] * qkv_w[c,k]
// Fused epilogue: scatter into q/k/v (b,h,n,f) layouts with
// q-bias + 1/sqrt(d) scale and v-bias applied.
// ============================================================
__global__ __launch_bounds__(256) void qkv_gemm(
        const float* __restrict__ A, const float* __restrict__ W,
        const float* __restrict__ qb, const float* __restrict__ vb)
{
    __shared__ float As[16][64];   // [k][m]
    __shared__ float Bs[16][64];   // [k][n]
    const int tid = threadIdx.x;
    const int tx = tid & 15, ty = tid >> 4;
    const int m0 = blockIdx.y * 64, n0 = blockIdx.x * 64;
    const int lm = tid >> 2;          // 0..63
    const int lk = (tid & 3) << 2;    // 0,4,8,12

    float acc[4][4] = {};
    for (int k0 = 0; k0 < FT; k0 += 16) {
        float4 a4 = make_float4(0.f, 0.f, 0.f, 0.f);
        if (m0 + lm < MROWS)
            a4 = *(const float4*)(A + (size_t)(m0 + lm) * FT + k0 + lk);
        As[lk+0][lm] = a4.x; As[lk+1][lm] = a4.y;
        As[lk+2][lm] = a4.z; As[lk+3][lm] = a4.w;
        float4 b4 = *(const float4*)(W + (size_t)(n0 + lm) * FT + k0 + lk);
        Bs[lk+0][lm] = b4.x; Bs[lk+1][lm] = b4.y;
        Bs[lk+2][lm] = b4.z; Bs[lk+3][lm] = b4.w;
        __syncthreads();
        #pragma unroll
        for (int k = 0; k < 16; k++) {
            float4 ra = *(const float4*)&As[k][ty << 2];
            float4 rb = *(const float4*)&Bs[k][tx << 2];
            float av[4] = {ra.x, ra.y, ra.z, ra.w};
            float bv[4] = {rb.x, rb.y, rb.z, rb.w};
            #pragma unroll
            for (int i = 0; i < 4; i++)
                #pragma unroll
                for (int j = 0; j < 4; j++)
                    acc[i][j] += av[i] * bv[j];
        }
        __syncthreads();
    }
    #pragma unroll
    for (int i = 0; i < 4; i++) {
        int m = m0 + (ty << 2) + i;
        if (m >= MROWS) break;
        int b = m / NTOK, n = m - b * NTOK;
        #pragma unroll
        for (int j = 0; j < 4; j++) {
            int c = n0 + (tx << 2) + j;
            int part = c / FT;
            int hc = c - part * FT;          // h*64 + f
            int h = hc >> 6, f = hc & 63;
            size_t o = ((size_t)(b * NH + h) * NTOK + n) * FH + f;
            float v = acc[i][j];
            if (part == 0)      g_q[o] = (v + qb[hc]) * 0.125f;
            else if (part == 1) g_k[o] = v;
            else                g_v[o] = v + vb[hc];
        }
    }
}

// ============================================================
// Kernel 2: fused flash-attention with relpos bias gather.
// One CTA = (b, h, 64-row Q tile). Online softmax over 17 key
// tiles of 64. Bias gathered per-element from relpos_index (L2)
// + relpos_table (L1).
// ============================================================
__global__ __launch_bounds__(256) void attn_kernel(
        const float* __restrict__ table, const int* __restrict__ rpi)
{
    __shared__ float Qt[64][64];   // [f][row]     (Q transposed)
    __shared__ float KV[64][64];   // K: [f][key]  then V: [key][f]
    __shared__ float Ps[64][64];   // [row][key]
    const int tid = threadIdx.x;
    const int tx = tid & 15, ty = tid >> 4;
    const int b = blockIdx.z, h = blockIdx.y;
    const int q0 = blockIdx.x * 64;
    const float* Qg = g_q + (size_t)(b * NH + h) * NTOK * FH;
    const float* Kg = g_k + (size_t)(b * NH + h) * NTOK * FH;
    const float* Vg = g_v + (size_t)(b * NH + h) * NTOK * FH;

    const int lrow = tid >> 2;           // 0..63
    const int lcol = (tid & 3) << 2;     // 0,4,8,12

    // load Q tile transposed: Qt[f][row]
    #pragma unroll
    for (int s = 0; s < 4; s++) {
        int f = lcol + s * 16;
        float4 v = make_float4(0.f, 0.f, 0.f, 0.f);
        if (q0 + lrow < NTOK)
            v = *(const float4*)(Qg + (size_t)(q0 + lrow) * FH + f);
        Qt[f+0][lrow] = v.x; Qt[f+1][lrow] = v.y;
        Qt[f+2][lrow] = v.z; Qt[f+3][lrow] = v.w;
    }

    float O[4][4] = {};
    float mr[4], ls[4];
    #pragma unroll
    for (int i = 0; i < 4; i++) { mr[i] = -1e30f; ls[i] = 0.f; }

    for (int jt = 0; jt < 17; jt++) {
        const int k0 = jt * 64;
        __syncthreads();                       // Q ready / prev PV done with KV
        // load K transposed: KV[f][key]
        #pragma unroll
        for (int s = 0; s < 4; s++) {
            int f = lcol + s * 16;
            float4 v = make_float4(0.f, 0.f, 0.f, 0.f);
            if (k0 + lrow < NTOK)
                v = *(const float4*)(Kg + (size_t)(k0 + lrow) * FH + f);
            KV[f+0][lrow] = v.x; KV[f+1][lrow] = v.y;
            KV[f+2][lrow] = v.z; KV[f+3][lrow] = v.w;
        }
        __syncthreads();
        // S = Q K^T (4x4 per thread)
        float S[4][4] = {};
        #pragma unroll 8
        for (int f = 0; f < 64; f++) {
            float4 ra = *(const float4*)&Qt[f][ty << 2];
            float4 rb = *(const float4*)&KV[f][tx << 2];
            float av[4] = {ra.x, ra.y, ra.z, ra.w};
            float bv[4] = {rb.x, rb.y, rb.z, rb.w};
            #pragma unroll
            for (int i = 0; i < 4; i++)
                #pragma unroll
                for (int j = 0; j < 4; j++)
                    S[i][j] += av[i] * bv[j];
        }
        // relpos bias + mask
        #pragma unroll
        for (int i = 0; i < 4; i++) {
            int qi = q0 + (ty << 2) + i;
            #pragma unroll
            for (int j = 0; j < 4; j++) {
                int kj = k0 + (tx << 2) + j;
                if (qi < NTOK && kj < NTOK)
                    S[i][j] += table[(size_t)rpi[(size_t)qi * NTOK + kj] * NH + h];
                else
                    S[i][j] = -1e30f;
            }
        }
        // online softmax update (row groups live on 16 lanes: lane bits 0..3 = tx)
        #pragma unroll
        for (int i = 0; i < 4; i++) {
            float rm = fmaxf(fmaxf(S[i][0], S[i][1]), fmaxf(S[i][2], S[i][3]));
            #pragma unroll
            for (int o = 8; o > 0; o >>= 1)
                rm = fmaxf(rm, __shfl_xor_sync(0xffffffffu, rm, o));
            float mnew = fmaxf(mr[i], rm);
            float alpha = __expf(mr[i] - mnew);
            mr[i] = mnew;
            float rs = 0.f;
            #pragma unroll
            for (int j = 0; j < 4; j++) {
                S[i][j] = __expf(S[i][j] - mnew);
                rs += S[i][j];
            }
            #pragma unroll
            for (int o = 8; o > 0; o >>= 1)
                rs += __shfl_xor_sync(0xffffffffu, rs, o);
            ls[i] = ls[i] * alpha + rs;
            #pragma unroll
            for (int j = 0; j < 4; j++) O[i][j] *= alpha;
        }
        __syncthreads();                       // everyone done reading KV as K
        // write P; load V into KV as [key][f]
        #pragma unroll
        for (int i = 0; i < 4; i++)
            #pragma unroll
            for (int j = 0; j < 4; j++)
                Ps[(ty << 2) + i][(tx << 2) + j] = S[i][j];
        #pragma unroll
        for (int s = 0; s < 4; s++) {
            int f = lcol + s * 16;
            float4 v = make_float4(0.f, 0.f, 0.f, 0.f);
            if (k0 + lrow < NTOK)
                v = *(const float4*)(Vg + (size_t)(k0 + lrow) * FH + f);
            *(float4*)&KV[lrow][f] = v;
        }
        __syncthreads();
        // O += P V
        #pragma unroll 8
        for (int k = 0; k < 64; k++) {
            float pv[4];
            #pragma unroll
            for (int i = 0; i < 4; i++) pv[i] = Ps[(ty << 2) + i][k];
            float4 rv = *(const float4*)&KV[k][tx << 2];
            float vv[4] = {rv.x, rv.y, rv.z, rv.w};
            #pragma unroll
            for (int i = 0; i < 4; i++)
                #pragma unroll
                for (int j = 0; j < 4; j++)
                    O[i][j] += pv[i] * vv[j];
        }
    }
    // epilogue: normalize, write (b, n, h*64+f)
    #pragma unroll
    for (int i = 0; i < 4; i++) {
        int qi = q0 + (ty << 2) + i;
        if (qi >= NTOK) break;
        float inv = 1.f / ls[i];
        #pragma unroll
        for (int j = 0; j < 4; j++)
            g_ao[(size_t)(b * NTOK + qi) * FT + h * FH + (tx << 2) + j]
                = O[i][j] * inv;
    }
}

// ============================================================
// Kernel 3: output projection. out[m,n] = sum_k ao[m,k]*proj_w[n,k] + b[n]
// ============================================================
__global__ __launch_bounds__(256) void proj_gemm(
        const float* __restrict__ W, const float* __restrict__ bias,
        float* __restrict__ out)
{
    __shared__ float As[16][64];
    __shared__ float Bs[16][64];
    const int tid = threadIdx.x;
    const int tx = tid & 15, ty = tid >> 4;
    const int m0 = blockIdx.y * 64, n0 = blockIdx.x * 64;
    const int lm = tid >> 2;
    const int lk = (tid & 3) << 2;

    float acc[4][4] = {};
    for (int k0 = 0; k0 < FT; k0 += 16) {
        float4 a4 = make_float4(0.f, 0.f, 0.f, 0.f);
        if (m0 + lm < MROWS)
            a4 = *(const float4*)(g_ao + (size_t)(m0 + lm) * FT + k0 + lk);
        As[lk+0][lm] = a4.x; As[lk+1][lm] = a4.y;
        As[lk+2][lm] = a4.z; As[lk+3][lm] = a4.w;
        float4 b4 = *(const float4*)(W + (size_t)(n0 + lm) * FT + k0 + lk);
        Bs[lk+0][lm] = b4.x; Bs[lk+1][lm] = b4.y;
        Bs[lk+2][lm] = b4.z; Bs[lk+3][lm] = b4.w;
        __syncthreads();
        #pragma unroll
        for (int k = 0; k < 16; k++) {
            float4 ra = *(const float4*)&As[k][ty << 2];
            float4 rb = *(const float4*)&Bs[k][tx << 2];
            float av[4] = {ra.x, ra.y, ra.z, ra.w};
            float bv[4] = {rb.x, rb.y, rb.z, rb.w};
            #pragma unroll
            for (int i = 0; i < 4; i++)
                #pragma unroll
                for (int j = 0; j < 4; j++)
                    acc[i][j] += av[i] * bv[j];
        }
        __syncthreads();
    }
    #pragma unroll
    for (int i = 0; i < 4; i++) {
        int m = m0 + (ty << 2) + i;
        if (m >= MROWS) break;
        #pragma unroll
        for (int j = 0; j < 4; j++) {
            int c = n0 + (tx << 2) + j;
            out[(size_t)m * FT + c] = acc[i][j] + bias[c];
        }
    }
}

// ============================================================
extern "C" void kernel_launch(void* const* d_in, const int* in_sizes, int n_in,
                              void* d_out, int out_size)
{
    const float* tokens = (const float*)d_in[0];
    const float* qkv_w  = (const float*)d_in[1];
    const float* q_bias = (const float*)d_in[2];
    const float* v_bias = (const float*)d_in[3];
    const float* table  = (const float*)d_in[4];
    const float* proj_w = (const float*)d_in[5];
    const float* proj_b = (const float*)d_in[6];
    const int*   rpi    = (const int*)d_in[7];
    float* out = (float*)d_out;

    dim3 blk(256);
    dim3 g1((3 * FT) / 64, (MROWS + 63) / 64);   // 36 x 129
    qkv_gemm<<<g1, blk>>>(tokens, qkv_w, q_bias, v_bias);

    dim3 g2((NTOK + 63) / 64, NH, BB);           // 17 x 12 x 8
    attn_kernel<<<g2, blk>>>(table, rpi);

    dim3 g3(FT / 64, (MROWS + 63) / 64);         // 12 x 129
    proj_gemm<<<g3, blk>>>(proj_w, proj_b, out);
}